// round 13
// baseline (speedup 1.0000x reference)
#include <cuda_runtime.h>
#include <cuda_fp16.h>
#include <cuda_bf16.h>
#include <cstdint>

#define N_NODES 100000
#define N_EDGES 1600000
#define D 128

#define SCAN_B 512
#define NUM_SCAN_BLOCKS ((N_NODES + SCAN_B - 1) / SCAN_B)   // 196

// Scratch (device globals: allocation-free)
__device__ __half g_h[(size_t)N_NODES * D];   // 25.6 MB, fp16 h_raw = xW + b (unscaled)
__device__ float  g_rs[N_NODES];              // rsqrt(max(deg_s,1))
__device__ int    g_deg_s[N_NODES];
__device__ int    g_deg_r[N_NODES];
__device__ int    g_off[N_NODES];             // after fill: END offset per node
__device__ int    g_bsum[NUM_SCAN_BLOCKS];
__device__ int    g_csr[N_EDGES];

// ---------------------------------------------------------------------------
__global__ void zero_kernel()
{
    const int stride = gridDim.x * blockDim.x;
    for (int j = blockIdx.x * blockDim.x + threadIdx.x; j < N_NODES; j += stride) {
        g_deg_s[j] = 0;
        g_deg_r[j] = 0;
    }
}

__global__ void degree_kernel(const int* __restrict__ s, const int* __restrict__ r)
{
    int i = blockIdx.x * blockDim.x + threadIdx.x;
    if (i < N_EDGES) {
        atomicAdd(&g_deg_s[s[i]], 1);
        atomicAdd(&g_deg_r[r[i]], 1);
    }
}

// ---------------------------------------------------------------------------
// scan_part also materializes g_rs (one thread per node — free ride)
// ---------------------------------------------------------------------------
__global__ void scan_part_kernel()
{
    __shared__ int sh[SCAN_B];
    const int t = threadIdx.x;
    const int idx = blockIdx.x * SCAN_B + t;
    const int v = (idx < N_NODES) ? g_deg_r[idx] : 0;
    if (idx < N_NODES)
        g_rs[idx] = rsqrtf(fmaxf((float)g_deg_s[idx], 1.0f));
    sh[t] = v;
    __syncthreads();
#pragma unroll
    for (int o = 1; o < SCAN_B; o <<= 1) {
        int x = (t >= o) ? sh[t - o] : 0;
        __syncthreads();
        sh[t] += x;
        __syncthreads();
    }
    if (idx < N_NODES) g_off[idx] = sh[t] - v;
    if (t == SCAN_B - 1) g_bsum[blockIdx.x] = sh[t];
}

__global__ void scan_add_kernel()
{
    __shared__ int red[32];
    const int t  = threadIdx.x;
    const int sb = blockIdx.x >> 1;

    int v = (t < sb) ? g_bsum[t] : 0;
#pragma unroll
    for (int o = 16; o > 0; o >>= 1) v += __shfl_down_sync(0xffffffffu, v, o);
    if ((t & 31) == 0) red[t >> 5] = v;
    __syncthreads();
    if (t < 32) {
        int w = (t < 8) ? red[t] : 0;
#pragma unroll
        for (int o = 4; o > 0; o >>= 1) w += __shfl_down_sync(0xffffffffu, w, o);
        if (t == 0) red[0] = w;
    }
    __syncthreads();
    const int prefix = red[0];

    const int idx = blockIdx.x * 256 + t;
    if (idx < N_NODES) g_off[idx] += prefix;
}

__global__ void fill_kernel(const int* __restrict__ s, const int* __restrict__ r)
{
    const int i = blockIdx.x * blockDim.x + threadIdx.x;
    if (i < N_EDGES) {
        const int pos = atomicAdd(&g_off[r[i]], 1);
        g_csr[pos] = s[i];
    }
}

// ---------------------------------------------------------------------------
// fp16 tensor-core GEMM (m16n8k16, fp32 accumulate):
// h_raw = x @ W + bias  (UNscaled — no degree dependency), stored fp16.
// W (128x128) loaded ONCE into smem transposed as [n][k] half2 words.
// ---------------------------------------------------------------------------
#define GBM 128
#define GBK 32
#define AS_W 20
#define BS_W 68

__device__ __forceinline__ void mma_f16(float4& d,
                                        uint32_t a0, uint32_t a1, uint32_t a2, uint32_t a3,
                                        uint32_t b0, uint32_t b1)
{
    asm volatile(
        "mma.sync.aligned.m16n8k16.row.col.f32.f16.f16.f32 "
        "{%0,%1,%2,%3}, {%4,%5,%6,%7}, {%8,%9}, {%0,%1,%2,%3};"
        : "+f"(d.x), "+f"(d.y), "+f"(d.z), "+f"(d.w)
        : "r"(a0), "r"(a1), "r"(a2), "r"(a3), "r"(b0), "r"(b1));
}

__device__ __forceinline__ uint32_t h2bits(float lo, float hi)
{
    const __half2 h = __floats2half2_rn(lo, hi);
    return *reinterpret_cast<const uint32_t*>(&h);
}

__global__ __launch_bounds__(256, 2)
void gemm_tc_kernel(const float* __restrict__ x,
                    const float* __restrict__ w,
                    const float* __restrict__ bias)
{
    __shared__ uint32_t As[GBM][AS_W];   // 10.2 KB
    __shared__ uint32_t Bs[128][BS_W];   // 34.8 KB  (W transposed: [n][k/2])

    const int tid  = threadIdx.x;
    const int warp = tid >> 5;
    const int lane = tid & 31;
    const int gid  = lane >> 2;
    const int tig  = lane & 3;
    const int wm   = warp >> 1;
    const int wn   = warp & 1;
    const int row0 = blockIdx.x * GBM;

    // One-time: load whole W transposed into Bs[n][k/2] as half2
    {
        const int bn  = tid & 127;
        const int bk0 = (tid >> 7) * 64;
#pragma unroll
        for (int j = 0; j < 32; j++) {
            const int k = bk0 + j * 2;
            const float f0 = w[(size_t)k * D + bn];
            const float f1 = w[(size_t)(k + 1) * D + bn];
            Bs[bn][(bk0 >> 1) + j] = h2bits(f0, f1);
        }
    }

    float4 acc[2][8];
#pragma unroll
    for (int mt = 0; mt < 2; mt++)
#pragma unroll
        for (int nt = 0; nt < 8; nt++)
            acc[mt][nt] = make_float4(0.f, 0.f, 0.f, 0.f);

    __syncthreads();

    for (int kb = 0; kb < D; kb += GBK) {
#pragma unroll
        for (int p = 0; p < 4; p++) {
            const int idx = tid + p * 256;
            const int r   = idx >> 3;
            const int c   = (idx & 7) * 4;
            const int gr  = row0 + r;
            float4 v = make_float4(0.f, 0.f, 0.f, 0.f);
            if (gr < N_NODES)
                v = *reinterpret_cast<const float4*>(&x[(size_t)gr * D + kb + c]);
            As[r][(c >> 1) + 0] = h2bits(v.x, v.y);
            As[r][(c >> 1) + 1] = h2bits(v.z, v.w);
        }
        __syncthreads();

        const int kwb = kb >> 1;
#pragma unroll
        for (int kc = 0; kc < GBK; kc += 16) {
            const int kw = kc >> 1;
            uint32_t a[2][4];
#pragma unroll
            for (int mt = 0; mt < 2; mt++) {
                const int r = wm * 32 + mt * 16;
                a[mt][0] = As[r + gid    ][kw + tig    ];
                a[mt][1] = As[r + gid + 8][kw + tig    ];
                a[mt][2] = As[r + gid    ][kw + tig + 4];
                a[mt][3] = As[r + gid + 8][kw + tig + 4];
            }
#pragma unroll
            for (int nt = 0; nt < 8; nt++) {
                const int n0 = wn * 64 + nt * 8;
                const uint32_t b0 = Bs[n0 + gid][kwb + kw + tig    ];
                const uint32_t b1 = Bs[n0 + gid][kwb + kw + tig + 4];
                mma_f16(acc[0][nt], a[0][0], a[0][1], a[0][2], a[0][3], b0, b1);
                mma_f16(acc[1][nt], a[1][0], a[1][1], a[1][2], a[1][3], b0, b1);
            }
        }
        __syncthreads();
    }

    // Epilogue: + bias only (no degree scale), convert to fp16, store half2.
    float2 bv[8];
#pragma unroll
    for (int nt = 0; nt < 8; nt++) {
        const int n = wn * 64 + nt * 8 + tig * 2;
        bv[nt].x = __ldg(&bias[n]);
        bv[nt].y = __ldg(&bias[n + 1]);
    }
#pragma unroll
    for (int mt = 0; mt < 2; mt++) {
        const int rbase = row0 + wm * 32 + mt * 16;
        const int r0 = rbase + gid;
        const int r1 = rbase + gid + 8;
#pragma unroll
        for (int nt = 0; nt < 8; nt++) {
            const int n = wn * 64 + nt * 8 + tig * 2;
            if (r0 < N_NODES) {
                const __half2 o = __floats2half2_rn(acc[mt][nt].x + bv[nt].x,
                                                    acc[mt][nt].y + bv[nt].y);
                *reinterpret_cast<__half2*>(&g_h[(size_t)r0 * D + n]) = o;
            }
            if (r1 < N_NODES) {
                const __half2 o = __floats2half2_rn(acc[mt][nt].z + bv[nt].x,
                                                    acc[mt][nt].w + bv[nt].y);
                *reinterpret_cast<__half2*>(&g_h[(size_t)r1 * D + n]) = o;
            }
        }
    }
}

// ---------------------------------------------------------------------------
// Gather-aggregate: acc += rs_s[e] * h_raw[s_e] (fp32 FMA), final *rsqrt(deg_r).
// One warp per node; rs load is a warp-broadcast (1 wavefront).
// ---------------------------------------------------------------------------
__device__ __forceinline__ void acc_row_s(float4& acc, const uint2 raw, const float rs)
{
    const __half2 h0 = *reinterpret_cast<const __half2*>(&raw.x);
    const __half2 h1 = *reinterpret_cast<const __half2*>(&raw.y);
    const float2 f0 = __half22float2(h0);
    const float2 f1 = __half22float2(h1);
    acc.x = fmaf(rs, f0.x, acc.x);
    acc.y = fmaf(rs, f0.y, acc.y);
    acc.z = fmaf(rs, f1.x, acc.z);
    acc.w = fmaf(rs, f1.y, acc.w);
}

__global__ __launch_bounds__(256)
void gather_kernel(float* __restrict__ out)
{
    const int node = (blockIdx.x * blockDim.x + threadIdx.x) >> 5;
    const int lane = threadIdx.x & 31;
    if (node >= N_NODES) return;

    const int deg = g_deg_r[node];
    const int end = g_off[node];        // after fill, g_off holds row END
    const int beg = end - deg;

    float4 acc = make_float4(0.f, 0.f, 0.f, 0.f);
    const int fo = lane * 4;

    int j = beg;
    for (; j + 4 <= end; j += 4) {
        const int s0 = g_csr[j + 0];
        const int s1 = g_csr[j + 1];
        const int s2 = g_csr[j + 2];
        const int s3 = g_csr[j + 3];
        const uint2 v0 = *reinterpret_cast<const uint2*>(&g_h[(size_t)s0 * D + fo]);
        const uint2 v1 = *reinterpret_cast<const uint2*>(&g_h[(size_t)s1 * D + fo]);
        const uint2 v2 = *reinterpret_cast<const uint2*>(&g_h[(size_t)s2 * D + fo]);
        const uint2 v3 = *reinterpret_cast<const uint2*>(&g_h[(size_t)s3 * D + fo]);
        const float r0 = g_rs[s0];
        const float r1 = g_rs[s1];
        const float r2 = g_rs[s2];
        const float r3 = g_rs[s3];
        acc_row_s(acc, v0, r0);
        acc_row_s(acc, v1, r1);
        acc_row_s(acc, v2, r2);
        acc_row_s(acc, v3, r3);
    }
    for (; j < end; j++) {
        const int ss = g_csr[j];
        const uint2 v = *reinterpret_cast<const uint2*>(&g_h[(size_t)ss * D + fo]);
        acc_row_s(acc, v, g_rs[ss]);
    }

    const float sc = rsqrtf(fmaxf((float)deg, 1.0f));
    acc.x *= sc; acc.y *= sc; acc.z *= sc; acc.w *= sc;
    *reinterpret_cast<float4*>(&out[(size_t)node * D + fo]) = acc;
}

// ---------------------------------------------------------------------------
// Graph topology: GEMM is dependency-free -> forked at t=0 on side stream,
// fully parallel with zero -> degree -> scan -> fill. Join before gather.
// Streams/events are host objects created once (no device allocation).
// ---------------------------------------------------------------------------
extern "C" void kernel_launch(void* const* d_in, const int* in_sizes, int n_in,
                              void* d_out, int out_size)
{
    const float* x       = (const float*)d_in[0];
    const int*   senders = (const int*)d_in[1];
    const int*   recvs   = (const int*)d_in[2];
    const float* weight  = (const float*)d_in[4];
    const float* bias    = (const float*)d_in[5];
    float* out = (float*)d_out;

    static cudaStream_t side = nullptr;
    static cudaEvent_t  evA  = nullptr;
    static cudaEvent_t  evB  = nullptr;
    if (side == nullptr) {
        cudaStreamCreateWithFlags(&side, cudaStreamNonBlocking);
        cudaEventCreateWithFlags(&evA, cudaEventDisableTiming);
        cudaEventCreateWithFlags(&evB, cudaEventDisableTiming);
    }

    // Fork immediately: GEMM has no dependencies now.
    // (evA links stream0's capture-front to side so the fork is well-formed.)
    cudaEventRecord(evA, 0);
    cudaStreamWaitEvent(side, evA, 0);
    gemm_tc_kernel<<<(N_NODES + GBM - 1) / GBM, 256, 0, side>>>(x, weight, bias);
    cudaEventRecord(evB, side);

    // Main stream: CSR build chain
    zero_kernel<<<256, 256>>>();
    degree_kernel<<<(N_EDGES + 255) / 256, 256>>>(senders, recvs);
    scan_part_kernel<<<NUM_SCAN_BLOCKS, SCAN_B>>>();
    scan_add_kernel<<<(N_NODES + 255) / 256, 256>>>();
    fill_kernel<<<(N_EDGES + 255) / 256, 256>>>(senders, recvs);

    // Join: gather needs CSR + g_rs (main) and g_h (side)
    cudaStreamWaitEvent(0, evB, 0);
    gather_kernel<<<(N_NODES * 32 + 255) / 256, 256>>>(out);
}

// round 14
// speedup vs baseline: 1.0603x; 1.0603x over previous
#include <cuda_runtime.h>
#include <cuda_fp16.h>
#include <cuda_bf16.h>
#include <cstdint>

#define N_NODES 100000
#define N_EDGES 1600000
#define D 128

#define SCAN_B 512
#define NUM_SCAN_BLOCKS ((N_NODES + SCAN_B - 1) / SCAN_B)   // 196

// Scratch (device globals: allocation-free, zero-initialized at module load).
// g_deg_s / g_deg_r are re-zeroed by gather_kernel at the end of every call,
// so each call starts from a zeroed state without a dedicated zero pass.
__device__ __half g_h[(size_t)N_NODES * D];   // 25.6 MB, fp16 h = (xW+b)*rsqrt(deg_s)
__device__ int    g_deg_s[N_NODES];
__device__ int    g_deg_r[N_NODES];
__device__ int    g_off[N_NODES];             // after fill: END offset per node
__device__ int    g_bsum[NUM_SCAN_BLOCKS];
__device__ int    g_csr[N_EDGES];

// ---------------------------------------------------------------------------
__global__ void degree_kernel(const int* __restrict__ s, const int* __restrict__ r)
{
    int i = blockIdx.x * blockDim.x + threadIdx.x;
    if (i < N_EDGES) {
        atomicAdd(&g_deg_s[s[i]], 1);
        atomicAdd(&g_deg_r[r[i]], 1);
    }
}

// ---------------------------------------------------------------------------
__global__ void scan_part_kernel()
{
    __shared__ int sh[SCAN_B];
    const int t = threadIdx.x;
    const int idx = blockIdx.x * SCAN_B + t;
    const int v = (idx < N_NODES) ? g_deg_r[idx] : 0;
    sh[t] = v;
    __syncthreads();
#pragma unroll
    for (int o = 1; o < SCAN_B; o <<= 1) {
        int x = (t >= o) ? sh[t - o] : 0;
        __syncthreads();
        sh[t] += x;
        __syncthreads();
    }
    if (idx < N_NODES) g_off[idx] = sh[t] - v;
    if (t == SCAN_B - 1) g_bsum[blockIdx.x] = sh[t];
}

__global__ void scan_add_kernel()
{
    __shared__ int red[32];
    const int t  = threadIdx.x;
    const int sb = blockIdx.x >> 1;

    int v = (t < sb) ? g_bsum[t] : 0;
#pragma unroll
    for (int o = 16; o > 0; o >>= 1) v += __shfl_down_sync(0xffffffffu, v, o);
    if ((t & 31) == 0) red[t >> 5] = v;
    __syncthreads();
    if (t < 32) {
        int w = (t < 8) ? red[t] : 0;
#pragma unroll
        for (int o = 4; o > 0; o >>= 1) w += __shfl_down_sync(0xffffffffu, w, o);
        if (t == 0) red[0] = w;
    }
    __syncthreads();
    const int prefix = red[0];

    const int idx = blockIdx.x * 256 + t;
    if (idx < N_NODES) g_off[idx] += prefix;
}

__global__ void fill_kernel(const int* __restrict__ s, const int* __restrict__ r)
{
    const int i = blockIdx.x * blockDim.x + threadIdx.x;
    if (i < N_EDGES) {
        const int pos = atomicAdd(&g_off[r[i]], 1);
        g_csr[pos] = s[i];
    }
}

// ---------------------------------------------------------------------------
// fp16 tensor-core GEMM (m16n8k16, fp32 accumulate):
// h = (x @ W + bias) * rsqrt(max(deg_s,1)), stored fp16.
// W (128x128) loaded ONCE into smem transposed as [n][k] half2 words.
// ---------------------------------------------------------------------------
#define GBM 128
#define GBK 32
#define AS_W 20
#define BS_W 68

__device__ __forceinline__ void mma_f16(float4& d,
                                        uint32_t a0, uint32_t a1, uint32_t a2, uint32_t a3,
                                        uint32_t b0, uint32_t b1)
{
    asm volatile(
        "mma.sync.aligned.m16n8k16.row.col.f32.f16.f16.f32 "
        "{%0,%1,%2,%3}, {%4,%5,%6,%7}, {%8,%9}, {%0,%1,%2,%3};"
        : "+f"(d.x), "+f"(d.y), "+f"(d.z), "+f"(d.w)
        : "r"(a0), "r"(a1), "r"(a2), "r"(a3), "r"(b0), "r"(b1));
}

__device__ __forceinline__ uint32_t h2bits(float lo, float hi)
{
    const __half2 h = __floats2half2_rn(lo, hi);
    return *reinterpret_cast<const uint32_t*>(&h);
}

__global__ __launch_bounds__(256, 2)
void gemm_tc_kernel(const float* __restrict__ x,
                    const float* __restrict__ w,
                    const float* __restrict__ bias)
{
    __shared__ uint32_t As[GBM][AS_W];   // 10.2 KB
    __shared__ uint32_t Bs[128][BS_W];   // 34.8 KB  (W transposed: [n][k/2])

    const int tid  = threadIdx.x;
    const int warp = tid >> 5;
    const int lane = tid & 31;
    const int gid  = lane >> 2;
    const int tig  = lane & 3;
    const int wm   = warp >> 1;
    const int wn   = warp & 1;
    const int row0 = blockIdx.x * GBM;

    // One-time: load whole W transposed into Bs[n][k/2] as half2
    {
        const int bn  = tid & 127;
        const int bk0 = (tid >> 7) * 64;
#pragma unroll
        for (int j = 0; j < 32; j++) {
            const int k = bk0 + j * 2;
            const float f0 = w[(size_t)k * D + bn];
            const float f1 = w[(size_t)(k + 1) * D + bn];
            Bs[bn][(bk0 >> 1) + j] = h2bits(f0, f1);
        }
    }

    float4 acc[2][8];
#pragma unroll
    for (int mt = 0; mt < 2; mt++)
#pragma unroll
        for (int nt = 0; nt < 8; nt++)
            acc[mt][nt] = make_float4(0.f, 0.f, 0.f, 0.f);

    __syncthreads();

    for (int kb = 0; kb < D; kb += GBK) {
#pragma unroll
        for (int p = 0; p < 4; p++) {
            const int idx = tid + p * 256;
            const int r   = idx >> 3;
            const int c   = (idx & 7) * 4;
            const int gr  = row0 + r;
            float4 v = make_float4(0.f, 0.f, 0.f, 0.f);
            if (gr < N_NODES)
                v = *reinterpret_cast<const float4*>(&x[(size_t)gr * D + kb + c]);
            As[r][(c >> 1) + 0] = h2bits(v.x, v.y);
            As[r][(c >> 1) + 1] = h2bits(v.z, v.w);
        }
        __syncthreads();

        const int kwb = kb >> 1;
#pragma unroll
        for (int kc = 0; kc < GBK; kc += 16) {
            const int kw = kc >> 1;
            uint32_t a[2][4];
#pragma unroll
            for (int mt = 0; mt < 2; mt++) {
                const int r = wm * 32 + mt * 16;
                a[mt][0] = As[r + gid    ][kw + tig    ];
                a[mt][1] = As[r + gid + 8][kw + tig    ];
                a[mt][2] = As[r + gid    ][kw + tig + 4];
                a[mt][3] = As[r + gid + 8][kw + tig + 4];
            }
#pragma unroll
            for (int nt = 0; nt < 8; nt++) {
                const int n0 = wn * 64 + nt * 8;
                const uint32_t b0 = Bs[n0 + gid][kwb + kw + tig    ];
                const uint32_t b1 = Bs[n0 + gid][kwb + kw + tig + 4];
                mma_f16(acc[0][nt], a[0][0], a[0][1], a[0][2], a[0][3], b0, b1);
                mma_f16(acc[1][nt], a[1][0], a[1][1], a[1][2], a[1][3], b0, b1);
            }
        }
        __syncthreads();
    }

    // Epilogue: bias + rsqrt(deg_s), convert to fp16, store half2.
    float2 bv[8];
#pragma unroll
    for (int nt = 0; nt < 8; nt++) {
        const int n = wn * 64 + nt * 8 + tig * 2;
        bv[nt].x = __ldg(&bias[n]);
        bv[nt].y = __ldg(&bias[n + 1]);
    }
#pragma unroll
    for (int mt = 0; mt < 2; mt++) {
        const int rbase = row0 + wm * 32 + mt * 16;
        const int r0 = rbase + gid;
        const int r1 = rbase + gid + 8;
        const float s0 = (r0 < N_NODES) ? rsqrtf(fmaxf((float)g_deg_s[r0], 1.0f)) : 0.f;
        const float s1 = (r1 < N_NODES) ? rsqrtf(fmaxf((float)g_deg_s[r1], 1.0f)) : 0.f;
#pragma unroll
        for (int nt = 0; nt < 8; nt++) {
            const int n = wn * 64 + nt * 8 + tig * 2;
            if (r0 < N_NODES) {
                const __half2 o = __floats2half2_rn((acc[mt][nt].x + bv[nt].x) * s0,
                                                    (acc[mt][nt].y + bv[nt].y) * s0);
                *reinterpret_cast<__half2*>(&g_h[(size_t)r0 * D + n]) = o;
            }
            if (r1 < N_NODES) {
                const __half2 o = __floats2half2_rn((acc[mt][nt].z + bv[nt].x) * s1,
                                                    (acc[mt][nt].w + bv[nt].y) * s1);
                *reinterpret_cast<__half2*>(&g_h[(size_t)r1 * D + n]) = o;
            }
        }
    }
}

// ---------------------------------------------------------------------------
// Gather-aggregate over fp16 h, fp32 accumulation. One warp per node.
// Tail: re-zero g_deg_s/g_deg_r for the next call (replaces zero_kernel;
// globals are load-time zeroed so the first call is correct too).
// ---------------------------------------------------------------------------
__device__ __forceinline__ void acc_row(float4& acc, const uint2 raw)
{
    const __half2 h0 = *reinterpret_cast<const __half2*>(&raw.x);
    const __half2 h1 = *reinterpret_cast<const __half2*>(&raw.y);
    const float2 f0 = __half22float2(h0);
    const float2 f1 = __half22float2(h1);
    acc.x += f0.x; acc.y += f0.y; acc.z += f1.x; acc.w += f1.y;
}

__global__ __launch_bounds__(256)
void gather_kernel(float* __restrict__ out)
{
    const int node = (blockIdx.x * blockDim.x + threadIdx.x) >> 5;
    const int lane = threadIdx.x & 31;
    if (node >= N_NODES) return;

    const int deg = g_deg_r[node];
    const int end = g_off[node];        // after fill, g_off holds row END
    const int beg = end - deg;

    // Reset degree counters for the next call (values already consumed;
    // g_deg_s was consumed by gemm epilogue which completed before this
    // kernel via the event join).
    if (lane == 0) g_deg_r[node] = 0;
    if (lane == 1) g_deg_s[node] = 0;

    float4 acc = make_float4(0.f, 0.f, 0.f, 0.f);
    const int fo = lane * 4;

    int j = beg;
    for (; j + 4 <= end; j += 4) {
        const int s0 = g_csr[j + 0];
        const int s1 = g_csr[j + 1];
        const int s2 = g_csr[j + 2];
        const int s3 = g_csr[j + 3];
        const uint2 v0 = *reinterpret_cast<const uint2*>(&g_h[(size_t)s0 * D + fo]);
        const uint2 v1 = *reinterpret_cast<const uint2*>(&g_h[(size_t)s1 * D + fo]);
        const uint2 v2 = *reinterpret_cast<const uint2*>(&g_h[(size_t)s2 * D + fo]);
        const uint2 v3 = *reinterpret_cast<const uint2*>(&g_h[(size_t)s3 * D + fo]);
        acc_row(acc, v0);
        acc_row(acc, v1);
        acc_row(acc, v2);
        acc_row(acc, v3);
    }
    for (; j < end; j++) {
        const int ss = g_csr[j];
        const uint2 v = *reinterpret_cast<const uint2*>(&g_h[(size_t)ss * D + fo]);
        acc_row(acc, v);
    }

    const float sc = rsqrtf(fmaxf((float)deg, 1.0f));
    acc.x *= sc; acc.y *= sc; acc.z *= sc; acc.w *= sc;
    *reinterpret_cast<float4*>(&out[(size_t)node * D + fo]) = acc;
}

// ---------------------------------------------------------------------------
// Topology (R12 known-good): degree -> fork GEMM (side) parallel to
// scan_part -> scan_add -> fill (main); join before gather.
// ---------------------------------------------------------------------------
extern "C" void kernel_launch(void* const* d_in, const int* in_sizes, int n_in,
                              void* d_out, int out_size)
{
    const float* x       = (const float*)d_in[0];
    const int*   senders = (const int*)d_in[1];
    const int*   recvs   = (const int*)d_in[2];
    const float* weight  = (const float*)d_in[4];
    const float* bias    = (const float*)d_in[5];
    float* out = (float*)d_out;

    static cudaStream_t side = nullptr;
    static cudaEvent_t  evA  = nullptr;
    static cudaEvent_t  evB  = nullptr;
    if (side == nullptr) {
        cudaStreamCreateWithFlags(&side, cudaStreamNonBlocking);
        cudaEventCreateWithFlags(&evA, cudaEventDisableTiming);
        cudaEventCreateWithFlags(&evB, cudaEventDisableTiming);
    }

    // Main stream: degree (arrays arrive zeroed — load-time or by prior call)
    degree_kernel<<<(N_EDGES + 255) / 256, 256>>>(senders, recvs);

    // Fork: GEMM on side stream (depends on degree via evA)
    cudaEventRecord(evA, 0);
    cudaStreamWaitEvent(side, evA, 0);
    gemm_tc_kernel<<<(N_NODES + GBM - 1) / GBM, 256, 0, side>>>(x, weight, bias);
    cudaEventRecord(evB, side);

    // Main stream continues with CSR build (independent of GEMM)
    scan_part_kernel<<<NUM_SCAN_BLOCKS, SCAN_B>>>();
    scan_add_kernel<<<(N_NODES + 255) / 256, 256>>>();
    fill_kernel<<<(N_EDGES + 255) / 256, 256>>>(senders, recvs);

    // Join: gather needs both branches
    cudaStreamWaitEvent(0, evB, 0);
    gather_kernel<<<(N_NODES * 32 + 255) / 256, 256>>>(out);
}